// round 1
// baseline (speedup 1.0000x reference)
#include <cuda_runtime.h>
#include <math.h>

// Problem constants (fixed by the dataset)
#define BB 4
#define NN 16384
#define DD 128
#define EE 1048576
#define BN 65536   // B*N

// ---------------- device scratch (no allocations allowed) ----------------
__device__ float g_deg[BN];
__device__ float g_norm[BN];
__device__ int   g_cnt[BN];
__device__ int   g_off[BN + 1];
__device__ int   g_cur[BN];
__device__ int   g_src[EE];     // flattened source node id (b*N + col) per CSR slot
__device__ float g_val[EE];     // edge value per CSR slot
__device__ float g_y[BN * DD];  // pre-normalized features (x@W)*norm  (32 MB)

// ---------------- kernels ----------------

__global__ void k_zero() {
    int i = blockIdx.x * blockDim.x + threadIdx.x;
    if (i < BN) { g_deg[i] = 0.f; g_cnt[i] = 0; }
}

__global__ void k_edges(const int* __restrict__ eb, const int* __restrict__ er,
                        const float* __restrict__ ev) {
    int e = blockIdx.x * blockDim.x + threadIdx.x;
    if (e < EE) {
        int d = eb[e] * NN + er[e];
        atomicAdd(&g_deg[d], fabsf(ev[e]));
        atomicAdd(&g_cnt[d], 1);
    }
}

__global__ void k_norm() {
    int i = blockIdx.x * blockDim.x + threadIdx.x;
    if (i < BN) g_norm[i] = rsqrtf(g_deg[i] + 1e-6f);
}

// Single-block exclusive scan over g_cnt (65536 ints), 1024 threads x 64 elems.
__global__ void k_scan() {
    __shared__ int s[1024];
    int t = threadIdx.x;
    int base = t * 64;
    int sum = 0;
#pragma unroll 8
    for (int i = 0; i < 64; i++) sum += g_cnt[base + i];
    s[t] = sum;
    __syncthreads();
    int mine = sum;
    for (int off = 1; off < 1024; off <<= 1) {
        int v = (t >= off) ? s[t - off] : 0;
        __syncthreads();
        s[t] += v;
        __syncthreads();
    }
    int run = s[t] - mine;  // exclusive prefix of this thread's chunk
    for (int i = 0; i < 64; i++) {
        int c = g_cnt[base + i];
        g_off[base + i] = run;
        g_cur[base + i] = run;
        run += c;
    }
    if (t == 1023) g_off[BN] = run;  // == EE
}

__global__ void k_scatter(const int* __restrict__ eb, const int* __restrict__ er,
                          const int* __restrict__ ec, const float* __restrict__ ev) {
    int e = blockIdx.x * blockDim.x + threadIdx.x;
    if (e < EE) {
        int b = eb[e];
        int d = b * NN + er[e];
        int pos = atomicAdd(&g_cur[d], 1);
        g_src[pos] = b * NN + ec[e];
        g_val[pos] = ev[e];
    }
}

// GEMM: g_y[row] = (x[row] @ W) * g_norm[row]
// Block: 256 threads (8 warps). Dyn smem: W (128x128 f32, 64KB) + x tile (32x128, 16KB).
// Each warp computes 4 rows; each lane 4 consecutive output cols.
__global__ void k_gemm(const float* __restrict__ x, const float* __restrict__ W) {
    extern __shared__ float smem[];
    float* Ws = smem;             // 128*128
    float* xs = smem + 128 * 128; // 32*128

    // stage W once
    const float4* W4 = (const float4*)W;
    float4* Ws4 = (float4*)Ws;
    for (int i = threadIdx.x; i < 128 * 32; i += 256) Ws4[i] = W4[i];

    int warp = threadIdx.x >> 5;
    int lane = threadIdx.x & 31;
    int r0 = warp * 4;

    for (int g = blockIdx.x * 32; g < BN; g += gridDim.x * 32) {
        __syncthreads();  // protect xs reuse (and W staging on first iter)
        const float4* x4 = (const float4*)(x + (size_t)g * DD);
        float4* xs4 = (float4*)xs;
        for (int i = threadIdx.x; i < 32 * 32; i += 256) xs4[i] = x4[i];
        __syncthreads();

        float4 a0 = {0, 0, 0, 0}, a1 = {0, 0, 0, 0}, a2 = {0, 0, 0, 0}, a3 = {0, 0, 0, 0};
#pragma unroll 4
        for (int k = 0; k < 128; k++) {
            float4 wv = *(const float4*)&Ws[k * 128 + lane * 4];
            float s0 = xs[(r0 + 0) * 128 + k];
            float s1 = xs[(r0 + 1) * 128 + k];
            float s2 = xs[(r0 + 2) * 128 + k];
            float s3 = xs[(r0 + 3) * 128 + k];
            a0.x = fmaf(s0, wv.x, a0.x); a0.y = fmaf(s0, wv.y, a0.y);
            a0.z = fmaf(s0, wv.z, a0.z); a0.w = fmaf(s0, wv.w, a0.w);
            a1.x = fmaf(s1, wv.x, a1.x); a1.y = fmaf(s1, wv.y, a1.y);
            a1.z = fmaf(s1, wv.z, a1.z); a1.w = fmaf(s1, wv.w, a1.w);
            a2.x = fmaf(s2, wv.x, a2.x); a2.y = fmaf(s2, wv.y, a2.y);
            a2.z = fmaf(s2, wv.z, a2.z); a2.w = fmaf(s2, wv.w, a2.w);
            a3.x = fmaf(s3, wv.x, a3.x); a3.y = fmaf(s3, wv.y, a3.y);
            a3.z = fmaf(s3, wv.z, a3.z); a3.w = fmaf(s3, wv.w, a3.w);
        }
        float4* y4 = (float4*)g_y;
        int row = g + r0;
        float n0 = g_norm[row + 0], n1 = g_norm[row + 1];
        float n2 = g_norm[row + 2], n3 = g_norm[row + 3];
        float4 o;
        o.x = a0.x * n0; o.y = a0.y * n0; o.z = a0.z * n0; o.w = a0.w * n0;
        y4[(size_t)(row + 0) * 32 + lane] = o;
        o.x = a1.x * n1; o.y = a1.y * n1; o.z = a1.z * n1; o.w = a1.w * n1;
        y4[(size_t)(row + 1) * 32 + lane] = o;
        o.x = a2.x * n2; o.y = a2.y * n2; o.z = a2.z * n2; o.w = a2.w * n2;
        y4[(size_t)(row + 2) * 32 + lane] = o;
        o.x = a3.x * n3; o.y = a3.y * n3; o.z = a3.z * n3; o.w = a3.w * n3;
        y4[(size_t)(row + 3) * 32 + lane] = o;
    }
}

// SpMM + epilogue: one warp per destination row.
// out[d] = relu( (sum_j val_j * y[src_j]) * norm[d] + b )
__global__ void k_spmm(const float* __restrict__ bias, float* __restrict__ out) {
    int wid = (blockIdx.x * blockDim.x + threadIdx.x) >> 5;
    int lane = threadIdx.x & 31;
    if (wid >= BN) return;
    int s0 = g_off[wid], s1 = g_off[wid + 1];
    const float4* y4 = (const float4*)g_y;
    float4 acc = {0, 0, 0, 0};
    for (int j = s0; j < s1; j++) {
        float v = g_val[j];
        int src = g_src[j];
        float4 yv = y4[(size_t)src * 32 + lane];
        acc.x = fmaf(v, yv.x, acc.x);
        acc.y = fmaf(v, yv.y, acc.y);
        acc.z = fmaf(v, yv.z, acc.z);
        acc.w = fmaf(v, yv.w, acc.w);
    }
    float nm = g_norm[wid];
    float4 bv = ((const float4*)bias)[lane];
    float4 o;
    o.x = fmaxf(fmaf(acc.x, nm, bv.x), 0.f);
    o.y = fmaxf(fmaf(acc.y, nm, bv.y), 0.f);
    o.z = fmaxf(fmaf(acc.z, nm, bv.z), 0.f);
    o.w = fmaxf(fmaf(acc.w, nm, bv.w), 0.f);
    ((float4*)out)[(size_t)wid * 32 + lane] = o;
}

// ---------------- launch ----------------

extern "C" void kernel_launch(void* const* d_in, const int* in_sizes, int n_in,
                              void* d_out, int out_size) {
    const float* x  = (const float*)d_in[0];
    const float* W  = (const float*)d_in[1];
    const float* b  = (const float*)d_in[2];
    const int*   eb = (const int*)d_in[3];
    const int*   er = (const int*)d_in[4];
    const int*   ec = (const int*)d_in[5];
    const float* ev = (const float*)d_in[6];
    float* out = (float*)d_out;

    static bool attr_set = false;
    const int gemm_smem = (128 * 128 + 32 * 128) * (int)sizeof(float);  // 80 KB
    if (!attr_set) {
        cudaFuncSetAttribute(k_gemm, cudaFuncAttributeMaxDynamicSharedMemorySize, gemm_smem);
        attr_set = true;
    }

    k_zero<<<BN / 256, 256>>>();
    k_edges<<<EE / 256, 256>>>(eb, er, ev);
    k_norm<<<BN / 256, 256>>>();
    k_scan<<<1, 1024>>>();
    k_scatter<<<EE / 256, 256>>>(eb, er, ec, ev);
    k_gemm<<<296, 256, gemm_smem>>>(x, W);
    k_spmm<<<BN * 32 / 256, 256>>>(b, out);
}

// round 3
// speedup vs baseline: 2.0512x; 2.0512x over previous
#include <cuda_runtime.h>
#include <math.h>

// Problem constants (fixed by the dataset)
#define BB 4
#define NN 16384
#define DD 128
#define EE 1048576
#define BN 65536   // B*N

// ---------------- device scratch (no allocations allowed) ----------------
__device__ float g_deg[BN];
__device__ float g_norm[BN];
__device__ int   g_cnt[BN];
__device__ int   g_off[BN + 1];
__device__ int   g_cur[BN];
__device__ int   g_blk[256];
__device__ int   g_src[EE];     // flattened source node id (b*N + col) per CSR slot
__device__ float g_val[EE];     // edge value per CSR slot
__device__ float g_y[BN * DD];  // pre-normalized features (x@W)*norm  (32 MB)

// ---------------- kernels ----------------

__global__ void k_zero() {
    int i = blockIdx.x * blockDim.x + threadIdx.x;
    if (i < BN) { g_deg[i] = 0.f; g_cnt[i] = 0; }
}

__global__ void k_edges(const int* __restrict__ eb, const int* __restrict__ er,
                        const float* __restrict__ ev) {
    int e = blockIdx.x * blockDim.x + threadIdx.x;
    if (e < EE) {
        int d = eb[e] * NN + er[e];
        atomicAdd(&g_deg[d], fabsf(ev[e]));
        atomicAdd(&g_cnt[d], 1);
    }
}

__global__ void k_norm() {
    int i = blockIdx.x * blockDim.x + threadIdx.x;
    if (i < BN) g_norm[i] = rsqrtf(g_deg[i] + 1e-6f);
}

// ---- hierarchical exclusive scan over g_cnt (65536 ints) ----
// Phase A: 256 blocks x 256 threads; block-local exclusive scan, store block sum.
__global__ void k_scan1() {
    __shared__ int warp_sums[8];
    int i = blockIdx.x * 256 + threadIdx.x;
    int lane = threadIdx.x & 31;
    int warp = threadIdx.x >> 5;
    int v = g_cnt[i];
    // warp inclusive scan
    int s = v;
#pragma unroll
    for (int o = 1; o < 32; o <<= 1) {
        int t = __shfl_up_sync(0xffffffffu, s, o);
        if (lane >= o) s += t;
    }
    if (lane == 31) warp_sums[warp] = s;
    __syncthreads();
    if (warp == 0) {
        int ws = (lane < 8) ? warp_sums[lane] : 0;
#pragma unroll
        for (int o = 1; o < 8; o <<= 1) {
            int t = __shfl_up_sync(0xffffffffu, ws, o);
            if (lane >= o) ws += t;
        }
        if (lane < 8) warp_sums[lane] = ws;
    }
    __syncthreads();
    int warp_off = (warp > 0) ? warp_sums[warp - 1] : 0;
    int excl = warp_off + s - v;   // exclusive within block
    g_off[i] = excl;               // phase C adds block offset
    if (threadIdx.x == 255) g_blk[blockIdx.x] = warp_off + s;  // block total
}

// Phase B: single block of 256 threads scans the 256 block sums (exclusive, in place).
__global__ void k_scan2() {
    __shared__ int warp_sums[8];
    int lane = threadIdx.x & 31;
    int warp = threadIdx.x >> 5;
    int v = g_blk[threadIdx.x];
    int s = v;
#pragma unroll
    for (int o = 1; o < 32; o <<= 1) {
        int t = __shfl_up_sync(0xffffffffu, s, o);
        if (lane >= o) s += t;
    }
    if (lane == 31) warp_sums[warp] = s;
    __syncthreads();
    if (warp == 0) {
        int ws = (lane < 8) ? warp_sums[lane] : 0;
#pragma unroll
        for (int o = 1; o < 8; o <<= 1) {
            int t = __shfl_up_sync(0xffffffffu, ws, o);
            if (lane >= o) ws += t;
        }
        if (lane < 8) warp_sums[lane] = ws;
    }
    __syncthreads();
    int warp_off = (warp > 0) ? warp_sums[warp - 1] : 0;
    g_blk[threadIdx.x] = warp_off + s - v;  // exclusive
    if (threadIdx.x == 0) g_off[BN] = EE;
}

// Phase C: add block offsets, init g_cur.
__global__ void k_scan3() {
    int i = blockIdx.x * 256 + threadIdx.x;
    int o = g_off[i] + g_blk[blockIdx.x];
    g_off[i] = o;
    g_cur[i] = o;
}

__global__ void k_scatter(const int* __restrict__ eb, const int* __restrict__ er,
                          const int* __restrict__ ec, const float* __restrict__ ev) {
    int e = blockIdx.x * blockDim.x + threadIdx.x;
    if (e < EE) {
        int b = eb[e];
        int d = b * NN + er[e];
        int pos = atomicAdd(&g_cur[d], 1);
        g_src[pos] = b * NN + ec[e];
        g_val[pos] = ev[e];
    }
}

// GEMM: g_y[row] = (x[row] @ W) * g_norm[row]
// Block: 256 threads (8 warps). Dyn smem: W (128x128 f32, 64KB) + x tile (32x128, 16KB).
// Each warp computes 4 rows; each lane 4 consecutive output cols.
__global__ void k_gemm(const float* __restrict__ x, const float* __restrict__ W) {
    extern __shared__ float smem[];
    float* Ws = smem;             // 128*128
    float* xs = smem + 128 * 128; // 32*128

    // stage W once
    const float4* W4 = (const float4*)W;
    float4* Ws4 = (float4*)Ws;
    for (int i = threadIdx.x; i < 128 * 32; i += 256) Ws4[i] = W4[i];

    int warp = threadIdx.x >> 5;
    int lane = threadIdx.x & 31;
    int r0 = warp * 4;

    for (int g = blockIdx.x * 32; g < BN; g += gridDim.x * 32) {
        __syncthreads();  // protect xs reuse (and W staging on first iter)
        const float4* x4 = (const float4*)(x + (size_t)g * DD);
        float4* xs4 = (float4*)xs;
        for (int i = threadIdx.x; i < 32 * 32; i += 256) xs4[i] = x4[i];
        __syncthreads();

        float4 a0 = {0, 0, 0, 0}, a1 = {0, 0, 0, 0}, a2 = {0, 0, 0, 0}, a3 = {0, 0, 0, 0};
#pragma unroll 4
        for (int k = 0; k < 128; k++) {
            float4 wv = *(const float4*)&Ws[k * 128 + lane * 4];
            float s0 = xs[(r0 + 0) * 128 + k];
            float s1 = xs[(r0 + 1) * 128 + k];
            float s2 = xs[(r0 + 2) * 128 + k];
            float s3 = xs[(r0 + 3) * 128 + k];
            a0.x = fmaf(s0, wv.x, a0.x); a0.y = fmaf(s0, wv.y, a0.y);
            a0.z = fmaf(s0, wv.z, a0.z); a0.w = fmaf(s0, wv.w, a0.w);
            a1.x = fmaf(s1, wv.x, a1.x); a1.y = fmaf(s1, wv.y, a1.y);
            a1.z = fmaf(s1, wv.z, a1.z); a1.w = fmaf(s1, wv.w, a1.w);
            a2.x = fmaf(s2, wv.x, a2.x); a2.y = fmaf(s2, wv.y, a2.y);
            a2.z = fmaf(s2, wv.z, a2.z); a2.w = fmaf(s2, wv.w, a2.w);
            a3.x = fmaf(s3, wv.x, a3.x); a3.y = fmaf(s3, wv.y, a3.y);
            a3.z = fmaf(s3, wv.z, a3.z); a3.w = fmaf(s3, wv.w, a3.w);
        }
        float4* y4 = (float4*)g_y;
        int row = g + r0;
        float n0 = g_norm[row + 0], n1 = g_norm[row + 1];
        float n2 = g_norm[row + 2], n3 = g_norm[row + 3];
        float4 o;
        o.x = a0.x * n0; o.y = a0.y * n0; o.z = a0.z * n0; o.w = a0.w * n0;
        y4[(size_t)(row + 0) * 32 + lane] = o;
        o.x = a1.x * n1; o.y = a1.y * n1; o.z = a1.z * n1; o.w = a1.w * n1;
        y4[(size_t)(row + 1) * 32 + lane] = o;
        o.x = a2.x * n2; o.y = a2.y * n2; o.z = a2.z * n2; o.w = a2.w * n2;
        y4[(size_t)(row + 2) * 32 + lane] = o;
        o.x = a3.x * n3; o.y = a3.y * n3; o.z = a3.z * n3; o.w = a3.w * n3;
        y4[(size_t)(row + 3) * 32 + lane] = o;
    }
}

// SpMM + epilogue: one warp per destination row.
// out[d] = relu( (sum_j val_j * y[src_j]) * norm[d] + b )
__global__ void k_spmm(const float* __restrict__ bias, float* __restrict__ out) {
    int wid = (blockIdx.x * blockDim.x + threadIdx.x) >> 5;
    int lane = threadIdx.x & 31;
    if (wid >= BN) return;
    int s0 = g_off[wid], s1 = g_off[wid + 1];
    const float4* y4 = (const float4*)g_y;
    float4 acc = {0, 0, 0, 0};
    for (int j = s0; j < s1; j++) {
        float v = g_val[j];
        int src = g_src[j];
        float4 yv = y4[(size_t)src * 32 + lane];
        acc.x = fmaf(v, yv.x, acc.x);
        acc.y = fmaf(v, yv.y, acc.y);
        acc.z = fmaf(v, yv.z, acc.z);
        acc.w = fmaf(v, yv.w, acc.w);
    }
    float nm = g_norm[wid];
    float4 bv = ((const float4*)bias)[lane];
    float4 o;
    o.x = fmaxf(fmaf(acc.x, nm, bv.x), 0.f);
    o.y = fmaxf(fmaf(acc.y, nm, bv.y), 0.f);
    o.z = fmaxf(fmaf(acc.z, nm, bv.z), 0.f);
    o.w = fmaxf(fmaf(acc.w, nm, bv.w), 0.f);
    ((float4*)out)[(size_t)wid * 32 + lane] = o;
}

// ---------------- launch ----------------

extern "C" void kernel_launch(void* const* d_in, const int* in_sizes, int n_in,
                              void* d_out, int out_size) {
    const float* x  = (const float*)d_in[0];
    const float* W  = (const float*)d_in[1];
    const float* b  = (const float*)d_in[2];
    const int*   eb = (const int*)d_in[3];
    const int*   er = (const int*)d_in[4];
    const int*   ec = (const int*)d_in[5];
    const float* ev = (const float*)d_in[6];
    float* out = (float*)d_out;

    static bool attr_set = false;
    const int gemm_smem = (128 * 128 + 32 * 128) * (int)sizeof(float);  // 80 KB
    if (!attr_set) {
        cudaFuncSetAttribute(k_gemm, cudaFuncAttributeMaxDynamicSharedMemorySize, gemm_smem);
        attr_set = true;
    }

    k_zero<<<BN / 256, 256>>>();
    k_edges<<<EE / 256, 256>>>(eb, er, ev);
    k_norm<<<BN / 256, 256>>>();
    k_scan1<<<256, 256>>>();
    k_scan2<<<1, 256>>>();
    k_scan3<<<256, 256>>>();
    k_scatter<<<EE / 256, 256>>>(eb, er, ec, ev);
    k_gemm<<<296, 256, gemm_smem>>>(x, W);
    k_spmm<<<BN * 32 / 256, 256>>>(b, out);
}

// round 5
// speedup vs baseline: 2.0832x; 1.0156x over previous
#include <cuda_runtime.h>
#include <stdint.h>
#include <math.h>

// Problem constants (fixed by the dataset)
#define BB 4
#define NN 16384
#define DD 128
#define EE 1048576
#define BN 65536   // B*N

// ---------------- device scratch (no allocations allowed) ----------------
__device__ float g_deg[BN];
__device__ float g_norm[BN];
__device__ int   g_cnt[BN];
__device__ int   g_off[BN + 1];
__device__ int   g_cur[BN];
__device__ int   g_blk[256];
__device__ int   g_src[EE];     // flattened source node id (b*N + col) per CSR slot
__device__ float g_val[EE];     // edge value per CSR slot
__device__ float g_y[BN * DD];  // pre-normalized features (x@W)*norm  (32 MB)

// ---------------- kernels ----------------

__global__ void k_zero() {
    int i = blockIdx.x * blockDim.x + threadIdx.x;
    if (i < BN) { g_deg[i] = 0.f; g_cnt[i] = 0; }
}

__global__ void k_edges(const int* __restrict__ eb, const int* __restrict__ er,
                        const float* __restrict__ ev) {
    int e = blockIdx.x * blockDim.x + threadIdx.x;
    if (e < EE) {
        int d = eb[e] * NN + er[e];
        atomicAdd(&g_deg[d], fabsf(ev[e]));
        atomicAdd(&g_cnt[d], 1);
    }
}

__global__ void k_norm() {
    int i = blockIdx.x * blockDim.x + threadIdx.x;
    if (i < BN) g_norm[i] = rsqrtf(g_deg[i] + 1e-6f);
}

// ---- hierarchical exclusive scan over g_cnt (65536 ints) ----
__global__ void k_scan1() {
    __shared__ int warp_sums[8];
    int i = blockIdx.x * 256 + threadIdx.x;
    int lane = threadIdx.x & 31;
    int warp = threadIdx.x >> 5;
    int v = g_cnt[i];
    int s = v;
#pragma unroll
    for (int o = 1; o < 32; o <<= 1) {
        int t = __shfl_up_sync(0xffffffffu, s, o);
        if (lane >= o) s += t;
    }
    if (lane == 31) warp_sums[warp] = s;
    __syncthreads();
    if (warp == 0) {
        int ws = (lane < 8) ? warp_sums[lane] : 0;
#pragma unroll
        for (int o = 1; o < 8; o <<= 1) {
            int t = __shfl_up_sync(0xffffffffu, ws, o);
            if (lane >= o) ws += t;
        }
        if (lane < 8) warp_sums[lane] = ws;
    }
    __syncthreads();
    int warp_off = (warp > 0) ? warp_sums[warp - 1] : 0;
    int excl = warp_off + s - v;
    g_off[i] = excl;
    if (threadIdx.x == 255) g_blk[blockIdx.x] = warp_off + s;
}

__global__ void k_scan2() {
    __shared__ int warp_sums[8];
    int lane = threadIdx.x & 31;
    int warp = threadIdx.x >> 5;
    int v = g_blk[threadIdx.x];
    int s = v;
#pragma unroll
    for (int o = 1; o < 32; o <<= 1) {
        int t = __shfl_up_sync(0xffffffffu, s, o);
        if (lane >= o) s += t;
    }
    if (lane == 31) warp_sums[warp] = s;
    __syncthreads();
    if (warp == 0) {
        int ws = (lane < 8) ? warp_sums[lane] : 0;
#pragma unroll
        for (int o = 1; o < 8; o <<= 1) {
            int t = __shfl_up_sync(0xffffffffu, ws, o);
            if (lane >= o) ws += t;
        }
        if (lane < 8) warp_sums[lane] = ws;
    }
    __syncthreads();
    int warp_off = (warp > 0) ? warp_sums[warp - 1] : 0;
    g_blk[threadIdx.x] = warp_off + s - v;
    if (threadIdx.x == 0) g_off[BN] = EE;
}

__global__ void k_scan3() {
    int i = blockIdx.x * 256 + threadIdx.x;
    int o = g_off[i] + g_blk[blockIdx.x];
    g_off[i] = o;
    g_cur[i] = o;
}

__global__ void k_scatter(const int* __restrict__ eb, const int* __restrict__ er,
                          const int* __restrict__ ec, const float* __restrict__ ev) {
    int e = blockIdx.x * blockDim.x + threadIdx.x;
    if (e < EE) {
        int b = eb[e];
        int d = b * NN + er[e];
        int pos = atomicAdd(&g_cur[d], 1);
        g_src[pos] = b * NN + ec[e];
        g_val[pos] = ev[e];
    }
}

// ---- tf32 tensor-core GEMM: g_y[row] = (x[row] @ W) * g_norm[row] ----
// Grid: 512 blocks, each one 128-row tile. Block 256 threads (8 warps).
// smem: xs[128][132] (A, row-major, tf32-rounded), Wt[128][132] (B as [n][k]).
// Padding 132 makes A and B fragment loads bank-conflict-free.
// Warp w computes rows [w*16, w*16+16) x all 128 cols via m16n8k8 mma.sync.

__device__ __forceinline__ uint32_t f2tf32(float v) {
    uint32_t t;
    asm("cvt.rna.tf32.f32 %0, %1;" : "=r"(t) : "f"(v));
    return t;
}

__global__ void __launch_bounds__(256, 1) k_gemm(const float* __restrict__ x,
                                                 const float* __restrict__ W) {
    extern __shared__ float smem[];
    float* xs = smem;              // [128][132]
    float* Wt = smem + 128 * 132;  // [n][k] = W[k][n], [128][132]
    int tid = threadIdx.x;
    int row0 = blockIdx.x * 128;

    // Stage W transposed (n-major) + round to tf32. Global read coalesced.
    for (int i = tid; i < 128 * 128; i += 256) {
        int k = i >> 7, n = i & 127;
        Wt[n * 132 + k] = __uint_as_float(f2tf32(W[i]));
    }
    // Stage x tile + round to tf32.
    const float* xrow = x + (size_t)row0 * 128;
    for (int i = tid; i < 128 * 128; i += 256) {
        xs[(i >> 7) * 132 + (i & 127)] = __uint_as_float(f2tf32(xrow[i]));
    }
    __syncthreads();

    int warp = tid >> 5;
    int lane = tid & 31;
    int gr = lane >> 2;   // group (0..7): row within fragment
    int tg = lane & 3;    // thread-in-group (0..3): k / col selector
    int rb = warp * 16;

    float acc[16][4];
#pragma unroll
    for (int t = 0; t < 16; t++) {
        acc[t][0] = 0.f; acc[t][1] = 0.f; acc[t][2] = 0.f; acc[t][3] = 0.f;
    }

#pragma unroll
    for (int k0 = 0; k0 < 128; k0 += 8) {
        uint32_t a0 = __float_as_uint(xs[(rb + gr) * 132 + k0 + tg]);
        uint32_t a1 = __float_as_uint(xs[(rb + 8 + gr) * 132 + k0 + tg]);
        uint32_t a2 = __float_as_uint(xs[(rb + gr) * 132 + k0 + 4 + tg]);
        uint32_t a3 = __float_as_uint(xs[(rb + 8 + gr) * 132 + k0 + 4 + tg]);
#pragma unroll
        for (int t = 0; t < 16; t++) {
            int n = t * 8 + gr;
            uint32_t b0 = __float_as_uint(Wt[n * 132 + k0 + tg]);
            uint32_t b1 = __float_as_uint(Wt[n * 132 + k0 + 4 + tg]);
            asm volatile(
                "mma.sync.aligned.m16n8k8.row.col.f32.tf32.tf32.f32 "
                "{%0,%1,%2,%3}, {%4,%5,%6,%7}, {%8,%9}, {%0,%1,%2,%3};"
                : "+f"(acc[t][0]), "+f"(acc[t][1]), "+f"(acc[t][2]), "+f"(acc[t][3])
                : "r"(a0), "r"(a1), "r"(a2), "r"(a3), "r"(b0), "r"(b1));
        }
    }

    // Epilogue: scale by norm, store. c0/c1 -> row rb+gr, cols 2*tg(+1); c2/c3 -> row rb+8+gr.
    int ra = row0 + rb + gr;
    int rc = ra + 8;
    float na = g_norm[ra];
    float nc = g_norm[rc];
    float2* ya = (float2*)(g_y + (size_t)ra * 128);
    float2* yc = (float2*)(g_y + (size_t)rc * 128);
#pragma unroll
    for (int t = 0; t < 16; t++) {
        int c2 = t * 4 + tg;  // float2 index: col = t*8 + tg*2
        float2 v;
        v.x = acc[t][0] * na; v.y = acc[t][1] * na;
        ya[c2] = v;
        v.x = acc[t][2] * nc; v.y = acc[t][3] * nc;
        yc[c2] = v;
    }
}

// SpMM + epilogue: one warp per destination row, 4-edge unroll for MLP.
__global__ void k_spmm(const float* __restrict__ bias, float* __restrict__ out) {
    int wid = (blockIdx.x * blockDim.x + threadIdx.x) >> 5;
    int lane = threadIdx.x & 31;
    if (wid >= BN) return;
    int s0 = g_off[wid], s1 = g_off[wid + 1];
    const float4* y4 = (const float4*)g_y;
    float4 acc = {0, 0, 0, 0};
    int j = s0;
    for (; j + 4 <= s1; j += 4) {
        float v0 = g_val[j], v1 = g_val[j + 1], v2 = g_val[j + 2], v3 = g_val[j + 3];
        int a = g_src[j], b = g_src[j + 1], c = g_src[j + 2], d = g_src[j + 3];
        float4 y0 = y4[(size_t)a * 32 + lane];
        float4 y1 = y4[(size_t)b * 32 + lane];
        float4 y2 = y4[(size_t)c * 32 + lane];
        float4 y3 = y4[(size_t)d * 32 + lane];
        acc.x = fmaf(v0, y0.x, acc.x); acc.y = fmaf(v0, y0.y, acc.y);
        acc.z = fmaf(v0, y0.z, acc.z); acc.w = fmaf(v0, y0.w, acc.w);
        acc.x = fmaf(v1, y1.x, acc.x); acc.y = fmaf(v1, y1.y, acc.y);
        acc.z = fmaf(v1, y1.z, acc.z); acc.w = fmaf(v1, y1.w, acc.w);
        acc.x = fmaf(v2, y2.x, acc.x); acc.y = fmaf(v2, y2.y, acc.y);
        acc.z = fmaf(v2, y2.z, acc.z); acc.w = fmaf(v2, y2.w, acc.w);
        acc.x = fmaf(v3, y3.x, acc.x); acc.y = fmaf(v3, y3.y, acc.y);
        acc.z = fmaf(v3, y3.z, acc.z); acc.w = fmaf(v3, y3.w, acc.w);
    }
    for (; j < s1; j++) {
        float v = g_val[j];
        int src = g_src[j];
        float4 yv = y4[(size_t)src * 32 + lane];
        acc.x = fmaf(v, yv.x, acc.x); acc.y = fmaf(v, yv.y, acc.y);
        acc.z = fmaf(v, yv.z, acc.z); acc.w = fmaf(v, yv.w, acc.w);
    }
    float nm = g_norm[wid];
    float4 bv = ((const float4*)bias)[lane];
    float4 o;
    o.x = fmaxf(fmaf(acc.x, nm, bv.x), 0.f);
    o.y = fmaxf(fmaf(acc.y, nm, bv.y), 0.f);
    o.z = fmaxf(fmaf(acc.z, nm, bv.z), 0.f);
    o.w = fmaxf(fmaf(acc.w, nm, bv.w), 0.f);
    ((float4*)out)[(size_t)wid * 32 + lane] = o;
}

// ---------------- launch ----------------

extern "C" void kernel_launch(void* const* d_in, const int* in_sizes, int n_in,
                              void* d_out, int out_size) {
    const float* x  = (const float*)d_in[0];
    const float* W  = (const float*)d_in[1];
    const float* b  = (const float*)d_in[2];
    const int*   eb = (const int*)d_in[3];
    const int*   er = (const int*)d_in[4];
    const int*   ec = (const int*)d_in[5];
    const float* ev = (const float*)d_in[6];
    float* out = (float*)d_out;

    static bool attr_set = false;
    const int gemm_smem = 2 * 128 * 132 * (int)sizeof(float);  // 132 KB
    if (!attr_set) {
        cudaFuncSetAttribute(k_gemm, cudaFuncAttributeMaxDynamicSharedMemorySize, gemm_smem);
        attr_set = true;
    }

    k_zero<<<BN / 256, 256>>>();
    k_edges<<<EE / 256, 256>>>(eb, er, ev);
    k_norm<<<BN / 256, 256>>>();
    k_scan1<<<256, 256>>>();
    k_scan2<<<1, 256>>>();
    k_scan3<<<256, 256>>>();
    k_scatter<<<EE / 256, 256>>>(eb, er, ec, ev);
    k_gemm<<<BN / 128, 256, gemm_smem>>>(x, W);
    k_spmm<<<BN * 32 / 256, 256>>>(b, out);
}

// round 6
// speedup vs baseline: 2.5393x; 1.2189x over previous
#include <cuda_runtime.h>
#include <cuda_fp16.h>
#include <stdint.h>
#include <math.h>

// Problem constants (fixed by the dataset)
#define BB 4
#define NN 16384
#define DD 128
#define EE 1048576
#define BN 65536   // B*N

// ---------------- device scratch (no allocations allowed) ----------------
__device__ float g_deg[BN];
__device__ float g_norm[BN];
__device__ int   g_cnt[BN];
__device__ int   g_off[BN + 1];
__device__ int   g_cur[BN];
__device__ int   g_blk[256];
__device__ uint2 g_edge[EE];      // AoS: {src_flat, f32 bits of val*norm_src}
__device__ __half g_yh[BN * DD];  // support = x@W in fp16 (16 MB)

// ---------------- kernels ----------------

__global__ void k_zero() {
    int i = blockIdx.x * blockDim.x + threadIdx.x;
    if (i < BN) { g_deg[i] = 0.f; g_cnt[i] = 0; }
}

__global__ void k_edges(const int* __restrict__ eb, const int* __restrict__ er,
                        const float* __restrict__ ev) {
    int e = blockIdx.x * blockDim.x + threadIdx.x;
    if (e < EE) {
        int d = eb[e] * NN + er[e];
        atomicAdd(&g_deg[d], fabsf(ev[e]));
        atomicAdd(&g_cnt[d], 1);
    }
}

__global__ void k_norm() {
    int i = blockIdx.x * blockDim.x + threadIdx.x;
    if (i < BN) g_norm[i] = rsqrtf(g_deg[i] + 1e-6f);
}

// ---- hierarchical exclusive scan over g_cnt (65536 ints) ----
__global__ void k_scan1() {
    __shared__ int warp_sums[8];
    int i = blockIdx.x * 256 + threadIdx.x;
    int lane = threadIdx.x & 31;
    int warp = threadIdx.x >> 5;
    int v = g_cnt[i];
    int s = v;
#pragma unroll
    for (int o = 1; o < 32; o <<= 1) {
        int t = __shfl_up_sync(0xffffffffu, s, o);
        if (lane >= o) s += t;
    }
    if (lane == 31) warp_sums[warp] = s;
    __syncthreads();
    if (warp == 0) {
        int ws = (lane < 8) ? warp_sums[lane] : 0;
#pragma unroll
        for (int o = 1; o < 8; o <<= 1) {
            int t = __shfl_up_sync(0xffffffffu, ws, o);
            if (lane >= o) ws += t;
        }
        if (lane < 8) warp_sums[lane] = ws;
    }
    __syncthreads();
    int warp_off = (warp > 0) ? warp_sums[warp - 1] : 0;
    int excl = warp_off + s - v;
    g_off[i] = excl;
    if (threadIdx.x == 255) g_blk[blockIdx.x] = warp_off + s;
}

__global__ void k_scan2() {
    __shared__ int warp_sums[8];
    int lane = threadIdx.x & 31;
    int warp = threadIdx.x >> 5;
    int v = g_blk[threadIdx.x];
    int s = v;
#pragma unroll
    for (int o = 1; o < 32; o <<= 1) {
        int t = __shfl_up_sync(0xffffffffu, s, o);
        if (lane >= o) s += t;
    }
    if (lane == 31) warp_sums[warp] = s;
    __syncthreads();
    if (warp == 0) {
        int ws = (lane < 8) ? warp_sums[lane] : 0;
#pragma unroll
        for (int o = 1; o < 8; o <<= 1) {
            int t = __shfl_up_sync(0xffffffffu, ws, o);
            if (lane >= o) ws += t;
        }
        if (lane < 8) warp_sums[lane] = ws;
    }
    __syncthreads();
    int warp_off = (warp > 0) ? warp_sums[warp - 1] : 0;
    g_blk[threadIdx.x] = warp_off + s - v;
    if (threadIdx.x == 0) g_off[BN] = EE;
}

__global__ void k_scan3() {
    int i = blockIdx.x * 256 + threadIdx.x;
    int o = g_off[i] + g_blk[blockIdx.x];
    g_off[i] = o;
    g_cur[i] = o;
}

// Scatter edges into CSR slots; fold norm[src] into the edge value.
__global__ void k_scatter(const int* __restrict__ eb, const int* __restrict__ er,
                          const int* __restrict__ ec, const float* __restrict__ ev) {
    int e = blockIdx.x * blockDim.x + threadIdx.x;
    if (e < EE) {
        int b = eb[e];
        int d = b * NN + er[e];
        int src = b * NN + ec[e];
        int pos = atomicAdd(&g_cur[d], 1);
        uint2 rec;
        rec.x = (unsigned)src;
        rec.y = __float_as_uint(ev[e] * g_norm[src]);
        g_edge[pos] = rec;
    }
}

// ---- tf32 tensor-core GEMM: g_yh[row] = fp16(x[row] @ W)  (no norm here) ----
__device__ __forceinline__ uint32_t f2tf32(float v) {
    uint32_t t;
    asm("cvt.rna.tf32.f32 %0, %1;" : "=r"(t) : "f"(v));
    return t;
}

__global__ void __launch_bounds__(256, 1) k_gemm(const float* __restrict__ x,
                                                 const float* __restrict__ W) {
    extern __shared__ float smem[];
    float* xs = smem;              // [128][132]
    float* Wt = smem + 128 * 132;  // [n][k] = W[k][n], [128][132]
    int tid = threadIdx.x;
    int row0 = blockIdx.x * 128;

    for (int i = tid; i < 128 * 128; i += 256) {
        int k = i >> 7, n = i & 127;
        Wt[n * 132 + k] = __uint_as_float(f2tf32(W[i]));
    }
    const float* xrow = x + (size_t)row0 * 128;
    for (int i = tid; i < 128 * 128; i += 256) {
        xs[(i >> 7) * 132 + (i & 127)] = __uint_as_float(f2tf32(xrow[i]));
    }
    __syncthreads();

    int warp = tid >> 5;
    int lane = tid & 31;
    int gr = lane >> 2;
    int tg = lane & 3;
    int rb = warp * 16;

    float acc[16][4];
#pragma unroll
    for (int t = 0; t < 16; t++) {
        acc[t][0] = 0.f; acc[t][1] = 0.f; acc[t][2] = 0.f; acc[t][3] = 0.f;
    }

#pragma unroll
    for (int k0 = 0; k0 < 128; k0 += 8) {
        uint32_t a0 = __float_as_uint(xs[(rb + gr) * 132 + k0 + tg]);
        uint32_t a1 = __float_as_uint(xs[(rb + 8 + gr) * 132 + k0 + tg]);
        uint32_t a2 = __float_as_uint(xs[(rb + gr) * 132 + k0 + 4 + tg]);
        uint32_t a3 = __float_as_uint(xs[(rb + 8 + gr) * 132 + k0 + 4 + tg]);
#pragma unroll
        for (int t = 0; t < 16; t++) {
            int n = t * 8 + gr;
            uint32_t b0 = __float_as_uint(Wt[n * 132 + k0 + tg]);
            uint32_t b1 = __float_as_uint(Wt[n * 132 + k0 + 4 + tg]);
            asm volatile(
                "mma.sync.aligned.m16n8k8.row.col.f32.tf32.tf32.f32 "
                "{%0,%1,%2,%3}, {%4,%5,%6,%7}, {%8,%9}, {%0,%1,%2,%3};"
                : "+f"(acc[t][0]), "+f"(acc[t][1]), "+f"(acc[t][2]), "+f"(acc[t][3])
                : "r"(a0), "r"(a1), "r"(a2), "r"(a3), "r"(b0), "r"(b1));
        }
    }

    // Epilogue: convert to fp16, store. acc[t][0..1] -> row rb+gr cols t*8+tg*2(+1);
    // acc[t][2..3] -> row rb+8+gr, same cols.
    int ra = row0 + rb + gr;
    int rc = ra + 8;
    __half2* ya = (__half2*)(g_yh + (size_t)ra * 128);
    __half2* yc = (__half2*)(g_yh + (size_t)rc * 128);
#pragma unroll
    for (int t = 0; t < 16; t++) {
        int c2 = t * 4 + tg;  // half2 index: col = t*8 + tg*2
        ya[c2] = __floats2half2_rn(acc[t][0], acc[t][1]);
        yc[c2] = __floats2half2_rn(acc[t][2], acc[t][3]);
    }
}

// SpMM + epilogue: one warp per destination row; fp16 y gather, 4-edge unroll.
// out[d] = relu( (sum_j val'_j * y[src_j]) * norm[d] + b )
__global__ void k_spmm(const float* __restrict__ bias, float* __restrict__ out) {
    int wid = (blockIdx.x * blockDim.x + threadIdx.x) >> 5;
    int lane = threadIdx.x & 31;
    if (wid >= BN) return;
    int s0 = g_off[wid], s1 = g_off[wid + 1];
    const uint2* y2 = (const uint2*)g_yh;  // 32 uint2 (= 4 halves each? no: 8B = 4 halves) per row
    float4 acc = {0, 0, 0, 0};
    int j = s0;
    for (; j + 4 <= s1; j += 4) {
        uint2 e0 = g_edge[j], e1 = g_edge[j + 1], e2 = g_edge[j + 2], e3 = g_edge[j + 3];
        uint2 r0 = y2[(size_t)e0.x * 32 + lane];
        uint2 r1 = y2[(size_t)e1.x * 32 + lane];
        uint2 r2 = y2[(size_t)e2.x * 32 + lane];
        uint2 r3 = y2[(size_t)e3.x * 32 + lane];
        float v0 = __uint_as_float(e0.y), v1 = __uint_as_float(e1.y);
        float v2 = __uint_as_float(e2.y), v3 = __uint_as_float(e3.y);
        float2 f;
        f = __half22float2(*(__half2*)&r0.x);
        acc.x = fmaf(v0, f.x, acc.x); acc.y = fmaf(v0, f.y, acc.y);
        f = __half22float2(*(__half2*)&r0.y);
        acc.z = fmaf(v0, f.x, acc.z); acc.w = fmaf(v0, f.y, acc.w);
        f = __half22float2(*(__half2*)&r1.x);
        acc.x = fmaf(v1, f.x, acc.x); acc.y = fmaf(v1, f.y, acc.y);
        f = __half22float2(*(__half2*)&r1.y);
        acc.z = fmaf(v1, f.x, acc.z); acc.w = fmaf(v1, f.y, acc.w);
        f = __half22float2(*(__half2*)&r2.x);
        acc.x = fmaf(v2, f.x, acc.x); acc.y = fmaf(v2, f.y, acc.y);
        f = __half22float2(*(__half2*)&r2.y);
        acc.z = fmaf(v2, f.x, acc.z); acc.w = fmaf(v2, f.y, acc.w);
        f = __half22float2(*(__half2*)&r3.x);
        acc.x = fmaf(v3, f.x, acc.x); acc.y = fmaf(v3, f.y, acc.y);
        f = __half22float2(*(__half2*)&r3.y);
        acc.z = fmaf(v3, f.x, acc.z); acc.w = fmaf(v3, f.y, acc.w);
    }
    for (; j < s1; j++) {
        uint2 e = g_edge[j];
        uint2 r = y2[(size_t)e.x * 32 + lane];
        float v = __uint_as_float(e.y);
        float2 f;
        f = __half22float2(*(__half2*)&r.x);
        acc.x = fmaf(v, f.x, acc.x); acc.y = fmaf(v, f.y, acc.y);
        f = __half22float2(*(__half2*)&r.y);
        acc.z = fmaf(v, f.x, acc.z); acc.w = fmaf(v, f.y, acc.w);
    }
    float nm = g_norm[wid];
    float4 bv = ((const float4*)bias)[lane];
    float4 o;
    o.x = fmaxf(fmaf(acc.x, nm, bv.x), 0.f);
    o.y = fmaxf(fmaf(acc.y, nm, bv.y), 0.f);
    o.z = fmaxf(fmaf(acc.z, nm, bv.z), 0.f);
    o.w = fmaxf(fmaf(acc.w, nm, bv.w), 0.f);
    ((float4*)out)[(size_t)wid * 32 + lane] = o;
}

// ---------------- launch ----------------

extern "C" void kernel_launch(void* const* d_in, const int* in_sizes, int n_in,
                              void* d_out, int out_size) {
    const float* x  = (const float*)d_in[0];
    const float* W  = (const float*)d_in[1];
    const float* b  = (const float*)d_in[2];
    const int*   eb = (const int*)d_in[3];
    const int*   er = (const int*)d_in[4];
    const int*   ec = (const int*)d_in[5];
    const float* ev = (const float*)d_in[6];
    float* out = (float*)d_out;

    static bool init_done = false;
    static cudaStream_t s2;
    static cudaEvent_t evA, evB;
    const int gemm_smem = 2 * 128 * 132 * (int)sizeof(float);  // 132 KB
    if (!init_done) {
        cudaFuncSetAttribute(k_gemm, cudaFuncAttributeMaxDynamicSharedMemorySize, gemm_smem);
        cudaStreamCreateWithFlags(&s2, cudaStreamNonBlocking);
        cudaEventCreateWithFlags(&evA, cudaEventDisableTiming);
        cudaEventCreateWithFlags(&evB, cudaEventDisableTiming);
        init_done = true;
    }

    // Fork: GEMM depends only on x,W -> run concurrently with the edge chain.
    cudaEventRecord(evA, 0);
    cudaStreamWaitEvent(s2, evA, 0);
    k_gemm<<<BN / 128, 256, gemm_smem, s2>>>(x, W);
    cudaEventRecord(evB, s2);

    // Edge-processing chain on the main stream.
    k_zero<<<BN / 256, 256>>>();
    k_edges<<<EE / 256, 256>>>(eb, er, ev);
    k_norm<<<BN / 256, 256>>>();
    k_scan1<<<256, 256>>>();
    k_scan2<<<1, 256>>>();
    k_scan3<<<256, 256>>>();
    k_scatter<<<EE / 256, 256>>>(eb, er, ec, ev);

    // Join: spmm needs both the CSR and g_yh.
    cudaStreamWaitEvent(0, evB, 0);
    k_spmm<<<BN * 32 / 256, 256>>>(b, out);
}